// round 16
// baseline (speedup 1.0000x reference)
#include <cuda_runtime.h>
#include <cuda_bf16.h>
#include <math.h>
#include <stdint.h>

#define B 4
#define T 128
#define NTOK 196
#define D 768
#define KF 16
#define KT 49
#define NF (B*KF)   // 64 selected frames
#define PROWS 256   // padded rows per frame for bf16 buffers (4 x 64)

// ---- output layout (float32, concatenated flat) ----
#define Z_N       (B*KF*KT*D)
#define FIDX_OFF  ((size_t)Z_N)
#define TIDX_OFF  (FIDX_OFF + B*KF)
#define FMASK_OFF (TIDX_OFF + NF*KT)
#define TMASK_OFF (FMASK_OFF + B*T)
#define TOTAL_OUT (TMASK_OFF + (size_t)B*T*NTOK)

typedef unsigned long long ull;

// ---- device scratch (zero-initialized at load; pad rows of g_xhi/g_xlo stay 0) ----
__device__ float g_frp[2][B*T*D];          // raw masked partial sums (3 MB)
__device__ float g_den[2][B*T];            // partial mask sums
__device__ int   g_frame_idx[NF];
__device__ int   g_token_idx[NF*KT];
__device__ float g_GFp[24][B*128*128];
__device__ float g_GF[B*128*128];          // reduced frame gram (256 KB)
__device__ float g_G[(size_t)NF*NTOK*NTOK];
__device__ __align__(128) __nv_bfloat16 g_xhi[(size_t)NF*PROWS*D];
__device__ __align__(128) __nv_bfloat16 g_xlo[(size_t)NF*PROWS*D];

__device__ __constant__ int2 c_tiles[10] = {
    {0,0},{0,1},{0,2},{0,3},{1,1},{1,2},{1,3},{2,2},{2,3},{3,3}
};

// ---- order-preserving float->uint key ----
__device__ __forceinline__ uint32_t fkey(float v) {
    uint32_t b = __float_as_uint(v);
    return ((int)b >= 0) ? (b | 0x80000000u) : ~b;
}
// ---- warp argmax via redux: strict-greater wins, ties -> lowest index ----
__device__ __forceinline__ int argmax_redux(float bv, int bi) {
    uint32_t k = fkey(bv), kmax, imin;
    asm volatile("redux.sync.max.u32 %0, %1, 0xffffffff;" : "=r"(kmax) : "r"(k));
    uint32_t c = (k == kmax) ? (uint32_t)bi : 0xffffffffu;
    asm volatile("redux.sync.min.u32 %0, %1, 0xffffffff;" : "=r"(imin) : "r"(c));
    return (int)imin;
}

__device__ __forceinline__ uint32_t smem_u32(const void* p) {
    uint32_t a;
    asm("{ .reg .u64 t; cvta.to.shared.u64 t, %1; cvt.u32.u64 %0, t; }" : "=r"(a) : "l"(p));
    return a;
}
__device__ __forceinline__ void ldsm4(uint32_t* r, uint32_t addr) {
    asm volatile("ldmatrix.sync.aligned.m8n8.x4.shared.b16 {%0,%1,%2,%3}, [%4];"
        : "=r"(r[0]), "=r"(r[1]), "=r"(r[2]), "=r"(r[3]) : "r"(addr));
}
__device__ __forceinline__ void mma16816(float* d, const uint32_t* a,
                                         uint32_t b0, uint32_t b1) {
    asm volatile("mma.sync.aligned.m16n8k16.row.col.f32.bf16.bf16.f32 "
        "{%0,%1,%2,%3}, {%4,%5,%6,%7}, {%8,%9}, {%0,%1,%2,%3};"
        : "+f"(d[0]), "+f"(d[1]), "+f"(d[2]), "+f"(d[3])
        : "r"(a[0]), "r"(a[1]), "r"(a[2]), "r"(a[3]), "r"(b0), "r"(b1));
}
__device__ __forceinline__ void cp16(uint32_t dst, const void* src) {
    asm volatile("cp.async.ca.shared.global [%0], [%1], 16;" :: "r"(dst), "l"(src));
}

// ================= K1: masked partial sums (two token-halves) + zero fmask =====
// grid (512, 2), 192 threads; block sums 98 tokens of one (b,t) frame.
__global__ void frp_partial_kernel(const float* __restrict__ x,
                                   const float* __restrict__ mask,
                                   float* __restrict__ out) {
    int bt = blockIdx.x, h = blockIdx.y;
    const float4* xp4 = (const float4*)(x + (size_t)bt * NTOK * D) + h * 98 * 192;
    const float* mp = mask + (size_t)bt * NTOK + h * 98;
    __shared__ float sm[98];
    int tid = threadIdx.x;
    if (h == 0 && tid == 0) out[FMASK_OFF + bt] = 0.f;   // fold: zero fmask
    if (tid < 98) sm[tid] = mp[tid];
    __syncthreads();
    if (tid == 0) {
        float s = 0.f;
        for (int n = 0; n < 98; n++) s += sm[n];
        g_den[h][bt] = s;
    }
    float ax = 0.f, ay = 0.f, az = 0.f, aw = 0.f;
#pragma unroll 14
    for (int n = 0; n < 98; n++) {
        float m = sm[n];
        float4 v = xp4[n * 192 + tid];
        ax += v.x * m; ay += v.y * m; az += v.z * m; aw += v.w * m;
    }
    float4* fr = (float4*)(g_frp[h] + (size_t)bt * D);
    fr[tid] = make_float4(ax, ay, az, aw);
}

// ================= K2: frame-gram partials (24-way k-split, inline combine) ====
__global__ __launch_bounds__(256, 1) void gf_partial_kernel() {
    int ks = blockIdx.x, b = blockIdx.y;
    const float* P0 = g_frp[0] + (size_t)b * T * D;
    const float* P1 = g_frp[1] + (size_t)b * T * D;
    __shared__ float As[128 * 18];
    __shared__ float s_inv[128];
    int tid = threadIdx.x;
    int ti = tid & 15, tj = tid >> 4;

    if (tid < 128) {
        float d = g_den[0][b * T + tid] + g_den[1][b * T + tid];
        s_inv[tid] = 1.0f / fmaxf(d, 1e-6f);
    }
    __syncthreads();

    ull acc[64];
#pragma unroll
    for (int i = 0; i < 64; i++) acc[i] = 0ull;

    for (int c = 0; c < 2; c++) {
        int k0 = ks * 32 + c * 16;
        __syncthreads();
#pragma unroll
        for (int r = 0; r < 8; r++) {
            int idx = tid + 256 * r;
            int row = idx >> 4, col = idx & 15;
            size_t o = (size_t)row * D + k0 + col;
            As[row * 18 + col] = (P0[o] + P1[o]) * s_inv[row];
        }
        __syncthreads();
#pragma unroll
        for (int kk = 0; kk < 16; kk += 2) {
            ull a2[8], b2[8];
#pragma unroll
            for (int u = 0; u < 8; u++)
                a2[u] = *(const ull*)&As[(ti + 16 * u) * 18 + kk];
#pragma unroll
            for (int v = 0; v < 8; v++)
                b2[v] = *(const ull*)&As[(tj + 16 * v) * 18 + kk];
#pragma unroll
            for (int u = 0; u < 8; u++)
#pragma unroll
                for (int v = 0; v < 8; v++)
                    asm("fma.rn.f32x2 %0, %1, %2, %0;"
                        : "+l"(acc[u * 8 + v]) : "l"(a2[u]), "l"(b2[v]));
        }
    }
    float* P = g_GFp[ks] + (size_t)b * 128 * 128;
#pragma unroll
    for (int u = 0; u < 8; u++) {
        int gi = ti + 16 * u;
#pragma unroll
        for (int v = 0; v < 8; v++) {
            int gj = tj + 16 * v;
            ull a = acc[u * 8 + v];
            float lo = __uint_as_float((unsigned)(a & 0xffffffffull));
            float hi = __uint_as_float((unsigned)(a >> 32));
            P[gi * 128 + gj] = lo + hi;
        }
    }
}

// ================= K3: reduce 24 frame-gram partials (parallel) =================
__global__ void gf_reduce_kernel() {
    int i = blockIdx.x * 256 + threadIdx.x;     // < 16384
    float4 a = ((const float4*)g_GFp[0])[i];
#pragma unroll
    for (int p = 1; p < 24; p++) {
        float4 v = ((const float4*)g_GFp[p])[i];
        a.x += v.x; a.y += v.y; a.z += v.z; a.w += v.w;
    }
    ((float4*)g_GF)[i] = a;
}

// ================= K4: novelty + frame FPS (per batch), 256-thread copy ========
__global__ void novelty_fps_kernel(float* __restrict__ out) {
    extern __shared__ float s_GF[];        // 128*128 floats
    int b = blockIdx.x, tid = threadIdx.x; // 256 threads

    float4* dst4 = (float4*)s_GF;
    const float4* src4 = (const float4*)(g_GF + (size_t)b * 16384);
#pragma unroll
    for (int i = 0; i < 16; i++) dst4[tid + 256 * i] = src4[tid + 256 * i];
    __syncthreads();
    if (tid >= 32) return;
    int lane = tid;

    float c[4];
#pragma unroll
    for (int r = 0; r < 4; r++) c[r] = s_GF[lane + 32 * r];
    float s = s_GF[0];
    float bestv = -3e38f; int besti = 0;
#pragma unroll
    for (int t = 0; t < T; t++) {
        int r = t >> 5, t2 = t & 31;
        float ct = __shfl_sync(0xffffffffu, c[r], t2);
        float gtt = s_GF[t * 128 + t];
        float nv = gtt - 2.f * ct + s;
        if (nv > bestv) { bestv = nv; besti = t; }
#pragma unroll
        for (int rr = 0; rr < 4; rr++)
            c[rr] = 0.9f * c[rr] + 0.1f * s_GF[t * 128 + lane + 32 * rr];
        s = 0.81f * s + 0.18f * ct + 0.01f * gtt;
    }

    int last = besti;
    if (lane == 0) {
        g_frame_idx[b * KF] = last;
        out[FIDX_OFF + b * KF] = (float)last;
        out[FMASK_OFF + b * T + last] = 1.0f;
    }

    float n[4], md[4];
#pragma unroll
    for (int r = 0; r < 4; r++) {
        int i = lane + 32 * r;
        n[r] = s_GF[i * 128 + i];
        md[r] = __int_as_float(0x7f800000);
    }
    for (int step = 1; step < KF; step++) {
        float nl = s_GF[last * 128 + last];
        float bv = -3e38f; int bi = 0x7fffffff;
#pragma unroll
        for (int r = 0; r < 4; r++) {
            int i = lane + 32 * r;
            float d = n[r] + nl - 2.f * s_GF[last * 128 + i];
            md[r] = fminf(md[r], d);
            if (i == last) md[r] = -1.f;
            if (md[r] > bv) { bv = md[r]; bi = i; }
        }
        last = argmax_redux(bv, bi);
        if (lane == 0) {
            g_frame_idx[b * KF + step] = last;
            out[FIDX_OFF + b * KF + step] = (float)last;
            out[FMASK_OFF + b * T + last] = 1.0f;
        }
    }
}

// ================= K5: split to bf16 hi/lo (float4 in, uint2 out) + zero tmask ====
__global__ void split_kernel(const float* __restrict__ x, float* __restrict__ out) {
    int f = blockIdx.x, row = blockIdx.y;
    int tid = threadIdx.x;
    if (tid < 8) out[TMASK_OFF + (blockIdx.x * 196 + blockIdx.y) * 8 + tid] = 0.f;

    int b = f >> 4, fidx = g_frame_idx[f];
    const float4* src = (const float4*)(x + (size_t)(b * T + fidx) * NTOK * D)
                      + row * 192;
    float4 v = src[tid];
    __nv_bfloat16 h0 = __float2bfloat16(v.x);
    __nv_bfloat16 h1 = __float2bfloat16(v.y);
    __nv_bfloat16 h2 = __float2bfloat16(v.z);
    __nv_bfloat16 h3 = __float2bfloat16(v.w);
    __nv_bfloat16 l0 = __float2bfloat16(v.x - __bfloat162float(h0));
    __nv_bfloat16 l1 = __float2bfloat16(v.y - __bfloat162float(h1));
    __nv_bfloat16 l2 = __float2bfloat16(v.z - __bfloat162float(h2));
    __nv_bfloat16 l3 = __float2bfloat16(v.w - __bfloat162float(h3));
    uint2 hv, lv;
    hv.x = ((uint32_t)__bfloat16_as_ushort(h1) << 16) | __bfloat16_as_ushort(h0);
    hv.y = ((uint32_t)__bfloat16_as_ushort(h3) << 16) | __bfloat16_as_ushort(h2);
    lv.x = ((uint32_t)__bfloat16_as_ushort(l1) << 16) | __bfloat16_as_ushort(l0);
    lv.y = ((uint32_t)__bfloat16_as_ushort(l3) << 16) | __bfloat16_as_ushort(l2);
    ((uint2*)(g_xhi + (size_t)f * PROWS * D))[row * 192 + tid] = hv;
    ((uint2*)(g_xlo + (size_t)f * PROWS * D))[row * 192 + tid] = lv;
}

// ================= K6: token Gram, 2-stage cp.async, 2x2 warp tiling, occ 5 ====
// Diagonal tiles (mi==nj): B aliases A in smem — half the loads, same math.
#define GDYN (2 * 4 * 4096)

__global__ __launch_bounds__(128, 5) void gram_hmma_kernel() {
    extern __shared__ __nv_bfloat16 sB[];
    uint32_t sb = smem_u32(sB);
    int tid = threadIdx.x;
    int w = tid >> 5, lane = tid & 31;
    int wm = w & 1, wn = w >> 1;
    int2 tI = c_tiles[blockIdx.x];
    int mi = tI.x, nj = tI.y;
    int f = blockIdx.y;
    bool diag = (mi == nj);

    const __nv_bfloat16* pAhi = g_xhi + (size_t)f * PROWS * D + (size_t)mi * 64 * D;
    const __nv_bfloat16* pAlo = g_xlo + (size_t)f * PROWS * D + (size_t)mi * 64 * D;
    const __nv_bfloat16* pBhi = g_xhi + (size_t)f * PROWS * D + (size_t)nj * 64 * D;
    const __nv_bfloat16* pBlo = g_xlo + (size_t)f * PROWS * D + (size_t)nj * 64 * D;

    int rbase = tid >> 2, chl = tid & 3;

    float acc[32];   // [au(2)][bj(4)][4]
#pragma unroll
    for (int i = 0; i < 32; i++) acc[i] = 0.f;

    int ntiles = diag ? 2 : 4;  // diag: only A tiles loaded; B aliases A
    auto issue = [&](int c, int stage) {
        int k0 = c * 32;
#pragma unroll
        for (int i = 0; i < 8; i++) {
            const int t = i >> 1;
            if (t >= ntiles) break;
            int row = (i & 1) * 32 + rbase;
            const __nv_bfloat16* src =
                (t == 0 ? pAhi : t == 1 ? pAlo : t == 2 ? pBhi : pBlo)
                + (size_t)row * D + k0 + chl * 8;
            uint32_t dst = sb + ((stage * 4 + t) << 12) + row * 64
                         + ((chl ^ ((row >> 1) & 3)) << 4);
            cp16(dst, src);
        }
        asm volatile("cp.async.commit_group;" ::: "memory");
    };

    issue(0, 0);

    int lrow = lane & 15, lhalf = lane >> 4;
    for (int c = 0; c < 24; c++) {
        int buf = c & 1;
        if (c + 1 < 24) {
            issue(c + 1, buf ^ 1);
            asm volatile("cp.async.wait_group 1;" ::: "memory");
        } else {
            asm volatile("cp.async.wait_group 0;" ::: "memory");
        }
        __syncthreads();

        uint32_t tAhi = sb + ((buf * 4 + 0) << 12);
        uint32_t tAlo = sb + ((buf * 4 + 1) << 12);
        uint32_t tBhi = diag ? tAhi : (sb + ((buf * 4 + 2) << 12));
        uint32_t tBlo = diag ? tAlo : (sb + ((buf * 4 + 3) << 12));
#pragma unroll
        for (int kh = 0; kh < 2; kh++) {
            int ch = kh * 2 + lhalf;
            int ar0 = wm * 32 + lrow, ar1 = ar0 + 16;
            int br0 = wn * 32 + lrow, br1 = br0 + 16;
            uint32_t ah0[4], ah1[4], al0[4], al1[4];
            uint32_t bh0[4], bh1[4], bl0[4], bl1[4];
            uint32_t ao0 = ar0 * 64 + ((ch ^ ((ar0 >> 1) & 3)) << 4);
            uint32_t ao1 = ar1 * 64 + ((ch ^ ((ar1 >> 1) & 3)) << 4);
            uint32_t bo0 = br0 * 64 + ((ch ^ ((br0 >> 1) & 3)) << 4);
            uint32_t bo1 = br1 * 64 + ((ch ^ ((br1 >> 1) & 3)) << 4);
            ldsm4(ah0, tAhi + ao0);
            ldsm4(ah1, tAhi + ao1);
            ldsm4(al0, tAlo + ao0);
            ldsm4(al1, tAlo + ao1);
            ldsm4(bh0, tBhi + bo0);
            ldsm4(bh1, tBhi + bo1);
            ldsm4(bl0, tBlo + bo0);
            ldsm4(bl1, tBlo + bo1);
#pragma unroll
            for (int au = 0; au < 2; au++) {
                const uint32_t* Ah = au ? ah1 : ah0;
                const uint32_t* Al = au ? al1 : al0;
                float* d = acc + au * 16;
                mma16816(d + 0,  Ah, bh0[0], bh0[2]);
                mma16816(d + 4,  Ah, bh0[1], bh0[3]);
                mma16816(d + 8,  Ah, bh1[0], bh1[2]);
                mma16816(d + 12, Ah, bh1[1], bh1[3]);
                mma16816(d + 0,  Ah, bl0[0], bl0[2]);
                mma16816(d + 4,  Ah, bl0[1], bl0[3]);
                mma16816(d + 8,  Ah, bl1[0], bl1[2]);
                mma16816(d + 12, Ah, bl1[1], bl1[3]);
                mma16816(d + 0,  Al, bh0[0], bh0[2]);
                mma16816(d + 4,  Al, bh0[1], bh0[3]);
                mma16816(d + 8,  Al, bh1[0], bh1[2]);
                mma16816(d + 12, Al, bh1[1], bh1[3]);
            }
        }
        __syncthreads();
    }

    // epilogue: direct write; mirror for nj>mi
    int gid = lane >> 2, tig = lane & 3;
    float* G = g_G + (size_t)f * NTOK * NTOK;
    bool mir = (nj > mi);
#pragma unroll
    for (int au = 0; au < 2; au++) {
        int gi0 = mi * 64 + wm * 32 + au * 16 + gid;
        int gi1 = gi0 + 8;
#pragma unroll
        for (int j = 0; j < 4; j++) {
            int gj = nj * 64 + wn * 32 + j * 8 + 2 * tig;
            if (gj < NTOK) {
                const float* a = acc + au * 16 + j * 4;
                float c0 = a[0], c1 = a[1], c2 = a[2], c3 = a[3];
                if (gi0 < NTOK) *(float2*)&G[(size_t)gi0 * NTOK + gj] = make_float2(c0, c1);
                if (gi1 < NTOK) *(float2*)&G[(size_t)gi1 * NTOK + gj] = make_float2(c2, c3);
                if (mir) {
                    if (gi0 < NTOK) {
                        G[(size_t)gj * NTOK + gi0] = c0;
                        G[(size_t)(gj + 1) * NTOK + gi0] = c1;
                    }
                    if (gi1 < NTOK) {
                        G[(size_t)gj * NTOK + gi1] = c2;
                        G[(size_t)(gj + 1) * NTOK + gi1] = c3;
                    }
                }
            }
        }
    }
}

// ================= K7: token FPS (per selected frame), 256 threads =============
#define GPAD 200
__global__ void token_fps_kernel(float* __restrict__ out) {
    extern __shared__ float Gs[];            // NTOK*GPAD floats
    __shared__ float s_rs[NTOK];

    int f = blockIdx.x, tid = threadIdx.x;   // 256 threads
    const float4* Gp4 = (const float4*)(g_G + (size_t)f * NTOK * NTOK);
    for (int i = tid; i < NTOK * 49; i += 256) {
        int row = i / 49;
        int c4 = i - row * 49;
        *(float4*)&Gs[row * GPAD + (c4 << 2)] = Gp4[i];
    }
    __syncthreads();
    if (tid < NTOK) {
        float r0 = 0.f, r1 = 0.f, r2 = 0.f, r3 = 0.f;
#pragma unroll 4
        for (int j = 0; j < 196; j += 4) {
            r0 += Gs[j * GPAD + tid];
            r1 += Gs[(j + 1) * GPAD + tid];
            r2 += Gs[(j + 2) * GPAD + tid];
            r3 += Gs[(j + 3) * GPAD + tid];
        }
        s_rs[tid] = (r0 + r1) + (r2 + r3);
    }
    __syncthreads();
    if (tid >= 32) return;
    int lane = tid;
    int fidx = g_frame_idx[f];
    int bb = f >> 4;
    size_t tmask_base = TMASK_OFF + ((size_t)(bb * T + fidx)) * NTOK;

    float n[7], md[7];
    float bv = -3e38f; int bi = 0x7fffffff;
#pragma unroll
    for (int q = 0; q < 7; q++) {
        int i = lane + 32 * q;
        bool val = i < NTOK;
        n[q]  = val ? Gs[i * GPAD + i] : 0.f;
        md[q] = val ? __int_as_float(0x7f800000) : -3e38f;
        float v = val ? (n[q] - s_rs[i] * (2.0f / 196.0f)) : -3e38f;
        if (v > bv) { bv = v; bi = i; }
    }
    int last = argmax_redux(bv, bi);
    if (lane == 0) {
        g_token_idx[f * KT] = last;
        out[TIDX_OFF + f * KT] = (float)last;
        out[tmask_base + last] = 1.0f;
    }

    for (int s = 1; s < KT; s++) {
        float nl = Gs[last * GPAD + last];
        bv = -3e38f; bi = 0x7fffffff;
#pragma unroll
        for (int q = 0; q < 7; q++) {
            int i = lane + 32 * q;
            bool val = i < NTOK;
            float g = val ? Gs[last * GPAD + i] : 0.f;
            float d = n[q] + nl - 2.f * g;
            md[q] = fminf(md[q], d);
            if (i == last) md[q] = -1.f;
            float mv = val ? md[q] : -3e38f;
            if (mv > bv) { bv = mv; bi = i; }
        }
        last = argmax_redux(bv, bi);
        if (lane == 0) {
            g_token_idx[f * KT + s] = last;
            out[TIDX_OFF + f * KT + s] = (float)last;
            out[tmask_base + last] = 1.0f;
        }
    }
}

// ================= K8: gather z =================
__global__ void gather_kernel(const float* __restrict__ x, float* __restrict__ out) {
    int row = blockIdx.x;
    int bk = row / KT;
    int t2 = row - bk * KT;
    int b = bk >> 4;
    int fidx = g_frame_idx[bk];
    int tok = g_token_idx[bk * KT + t2];
    const float4* src = (const float4*)(x + (((size_t)(b * T + fidx)) * NTOK + tok) * D);
    float4* dst = (float4*)(out + (size_t)row * D);
    dst[threadIdx.x] = src[threadIdx.x];
}

extern "C" void kernel_launch(void* const* d_in, const int* in_sizes, int n_in,
                              void* d_out, int out_size) {
    const float* x    = (const float*)d_in[0];
    const float* mask = (const float*)d_in[1];
    float* out = (float*)d_out;

    frp_partial_kernel<<<dim3(B * T, 2), 192>>>(x, mask, out);   // 1
    gf_partial_kernel<<<dim3(24, B), 256>>>();                   // 2
    gf_reduce_kernel<<<64, 256>>>();                             // 3

    cudaFuncSetAttribute(novelty_fps_kernel,
                         cudaFuncAttributeMaxDynamicSharedMemorySize, 128 * 128 * 4);
    novelty_fps_kernel<<<B, 256, 128 * 128 * 4>>>(out);          // 4 (ncu slot)

    split_kernel<<<dim3(NF, 196), 192>>>(x, out);                // 5

    cudaFuncSetAttribute(gram_hmma_kernel,
                         cudaFuncAttributeMaxDynamicSharedMemorySize, GDYN);
    gram_hmma_kernel<<<dim3(10, NF), 128, GDYN>>>();             // 6

    size_t dyn = (size_t)NTOK * GPAD * sizeof(float);            // 156,800 B
    cudaFuncSetAttribute(token_fps_kernel,
                         cudaFuncAttributeMaxDynamicSharedMemorySize, (int)dyn);
    token_fps_kernel<<<NF, 256, dyn>>>(out);                     // 7

    gather_kernel<<<B * KF * KT, 192>>>(x, out);                 // 8
}

// round 17
// speedup vs baseline: 1.0424x; 1.0424x over previous
#include <cuda_runtime.h>
#include <cuda_bf16.h>
#include <math.h>
#include <stdint.h>

#define B 4
#define T 128
#define NTOK 196
#define D 768
#define KF 16
#define KT 49
#define NF (B*KF)   // 64 selected frames
#define PROWS 256   // padded rows per frame for bf16 buffers (4 x 64)

// ---- output layout (float32, concatenated flat) ----
#define Z_N       (B*KF*KT*D)
#define FIDX_OFF  ((size_t)Z_N)
#define TIDX_OFF  (FIDX_OFF + B*KF)
#define FMASK_OFF (TIDX_OFF + NF*KT)
#define TMASK_OFF (FMASK_OFF + B*T)
#define TOTAL_OUT (TMASK_OFF + (size_t)B*T*NTOK)

typedef unsigned long long ull;

// ---- device scratch (zero-initialized at load; pad rows of g_xhi/g_xlo stay 0) ----
__device__ float g_frp[2][B*T*D];          // raw masked partial sums (3 MB)
__device__ float g_den[2][B*T];            // partial mask sums
__device__ int   g_frame_idx[NF];
__device__ int   g_token_idx[NF*KT];
__device__ float g_GFp[24][B*128*128];
__device__ float g_GF[B*128*128];          // reduced frame gram (256 KB)
__device__ float g_G[(size_t)NF*NTOK*NTOK];
__device__ __align__(128) __nv_bfloat16 g_xhi[(size_t)NF*PROWS*D];
__device__ __align__(128) __nv_bfloat16 g_xlo[(size_t)NF*PROWS*D];

__device__ __constant__ int2 c_tiles[10] = {
    {0,0},{0,1},{0,2},{0,3},{1,1},{1,2},{1,3},{2,2},{2,3},{3,3}
};

// ---- order-preserving float->uint key ----
__device__ __forceinline__ uint32_t fkey(float v) {
    uint32_t b = __float_as_uint(v);
    return ((int)b >= 0) ? (b | 0x80000000u) : ~b;
}
// ---- warp argmax via redux: strict-greater wins, ties -> lowest index ----
__device__ __forceinline__ int argmax_redux(float bv, int bi) {
    uint32_t k = fkey(bv), kmax, imin;
    asm volatile("redux.sync.max.u32 %0, %1, 0xffffffff;" : "=r"(kmax) : "r"(k));
    uint32_t c = (k == kmax) ? (uint32_t)bi : 0xffffffffu;
    asm volatile("redux.sync.min.u32 %0, %1, 0xffffffff;" : "=r"(imin) : "r"(c));
    return (int)imin;
}

__device__ __forceinline__ uint32_t smem_u32(const void* p) {
    uint32_t a;
    asm("{ .reg .u64 t; cvta.to.shared.u64 t, %1; cvt.u32.u64 %0, t; }" : "=r"(a) : "l"(p));
    return a;
}
__device__ __forceinline__ void ldsm4(uint32_t* r, uint32_t addr) {
    asm volatile("ldmatrix.sync.aligned.m8n8.x4.shared.b16 {%0,%1,%2,%3}, [%4];"
        : "=r"(r[0]), "=r"(r[1]), "=r"(r[2]), "=r"(r[3]) : "r"(addr));
}
__device__ __forceinline__ void mma16816(float* d, const uint32_t* a,
                                         uint32_t b0, uint32_t b1) {
    asm volatile("mma.sync.aligned.m16n8k16.row.col.f32.bf16.bf16.f32 "
        "{%0,%1,%2,%3}, {%4,%5,%6,%7}, {%8,%9}, {%0,%1,%2,%3};"
        : "+f"(d[0]), "+f"(d[1]), "+f"(d[2]), "+f"(d[3])
        : "r"(a[0]), "r"(a[1]), "r"(a[2]), "r"(a[3]), "r"(b0), "r"(b1));
}
__device__ __forceinline__ void cp16(uint32_t dst, const void* src) {
    asm volatile("cp.async.ca.shared.global [%0], [%1], 16;" :: "r"(dst), "l"(src));
}

// ================= K1: masked partial sums (two token-halves) + zero fmask =====
// grid (512, 2), 192 threads; block sums 98 tokens of one (b,t) frame.
__global__ void frp_partial_kernel(const float* __restrict__ x,
                                   const float* __restrict__ mask,
                                   float* __restrict__ out) {
    int bt = blockIdx.x, h = blockIdx.y;
    const float4* xp4 = (const float4*)(x + (size_t)bt * NTOK * D) + h * 98 * 192;
    const float* mp = mask + (size_t)bt * NTOK + h * 98;
    __shared__ float sm[98];
    int tid = threadIdx.x;
    if (h == 0 && tid == 0) out[FMASK_OFF + bt] = 0.f;   // fold: zero fmask
    if (tid < 98) sm[tid] = mp[tid];
    __syncthreads();
    if (tid == 0) {
        float s = 0.f;
        for (int n = 0; n < 98; n++) s += sm[n];
        g_den[h][bt] = s;
    }
    float ax = 0.f, ay = 0.f, az = 0.f, aw = 0.f;
#pragma unroll 14
    for (int n = 0; n < 98; n++) {
        float m = sm[n];
        float4 v = xp4[n * 192 + tid];
        ax += v.x * m; ay += v.y * m; az += v.z * m; aw += v.w * m;
    }
    float4* fr = (float4*)(g_frp[h] + (size_t)bt * D);
    fr[tid] = make_float4(ax, ay, az, aw);
}

// ================= K2: frame-gram partials (24-way k-split, inline combine) ====
__global__ __launch_bounds__(256, 1) void gf_partial_kernel() {
    int ks = blockIdx.x, b = blockIdx.y;
    const float* P0 = g_frp[0] + (size_t)b * T * D;
    const float* P1 = g_frp[1] + (size_t)b * T * D;
    __shared__ float As[128 * 18];
    __shared__ float s_inv[128];
    int tid = threadIdx.x;
    int ti = tid & 15, tj = tid >> 4;

    if (tid < 128) {
        float d = g_den[0][b * T + tid] + g_den[1][b * T + tid];
        s_inv[tid] = 1.0f / fmaxf(d, 1e-6f);
    }
    __syncthreads();

    ull acc[64];
#pragma unroll
    for (int i = 0; i < 64; i++) acc[i] = 0ull;

    for (int c = 0; c < 2; c++) {
        int k0 = ks * 32 + c * 16;
        __syncthreads();
#pragma unroll
        for (int r = 0; r < 8; r++) {
            int idx = tid + 256 * r;
            int row = idx >> 4, col = idx & 15;
            size_t o = (size_t)row * D + k0 + col;
            As[row * 18 + col] = (P0[o] + P1[o]) * s_inv[row];
        }
        __syncthreads();
#pragma unroll
        for (int kk = 0; kk < 16; kk += 2) {
            ull a2[8], b2[8];
#pragma unroll
            for (int u = 0; u < 8; u++)
                a2[u] = *(const ull*)&As[(ti + 16 * u) * 18 + kk];
#pragma unroll
            for (int v = 0; v < 8; v++)
                b2[v] = *(const ull*)&As[(tj + 16 * v) * 18 + kk];
#pragma unroll
            for (int u = 0; u < 8; u++)
#pragma unroll
                for (int v = 0; v < 8; v++)
                    asm("fma.rn.f32x2 %0, %1, %2, %0;"
                        : "+l"(acc[u * 8 + v]) : "l"(a2[u]), "l"(b2[v]));
        }
    }
    float* P = g_GFp[ks] + (size_t)b * 128 * 128;
#pragma unroll
    for (int u = 0; u < 8; u++) {
        int gi = ti + 16 * u;
#pragma unroll
        for (int v = 0; v < 8; v++) {
            int gj = tj + 16 * v;
            ull a = acc[u * 8 + v];
            float lo = __uint_as_float((unsigned)(a & 0xffffffffull));
            float hi = __uint_as_float((unsigned)(a >> 32));
            P[gi * 128 + gj] = lo + hi;
        }
    }
}

// ================= K3: reduce 24 frame-gram partials (parallel) =================
__global__ void gf_reduce_kernel() {
    int i = blockIdx.x * 256 + threadIdx.x;     // < 16384
    float4 a = ((const float4*)g_GFp[0])[i];
#pragma unroll
    for (int p = 1; p < 24; p++) {
        float4 v = ((const float4*)g_GFp[p])[i];
        a.x += v.x; a.y += v.y; a.z += v.z; a.w += v.w;
    }
    ((float4*)g_GF)[i] = a;
}

// ================= K4: novelty + frame FPS (per batch), 256-thread copy ========
__global__ void novelty_fps_kernel(float* __restrict__ out) {
    extern __shared__ float s_GF[];        // 128*128 floats
    int b = blockIdx.x, tid = threadIdx.x; // 256 threads

    float4* dst4 = (float4*)s_GF;
    const float4* src4 = (const float4*)(g_GF + (size_t)b * 16384);
#pragma unroll
    for (int i = 0; i < 16; i++) dst4[tid + 256 * i] = src4[tid + 256 * i];
    __syncthreads();
    if (tid >= 32) return;
    int lane = tid;

    float c[4];
#pragma unroll
    for (int r = 0; r < 4; r++) c[r] = s_GF[lane + 32 * r];
    float s = s_GF[0];
    float bestv = -3e38f; int besti = 0;
#pragma unroll
    for (int t = 0; t < T; t++) {
        int r = t >> 5, t2 = t & 31;
        float ct = __shfl_sync(0xffffffffu, c[r], t2);
        float gtt = s_GF[t * 128 + t];
        float nv = gtt - 2.f * ct + s;
        if (nv > bestv) { bestv = nv; besti = t; }
#pragma unroll
        for (int rr = 0; rr < 4; rr++)
            c[rr] = 0.9f * c[rr] + 0.1f * s_GF[t * 128 + lane + 32 * rr];
        s = 0.81f * s + 0.18f * ct + 0.01f * gtt;
    }

    int last = besti;
    if (lane == 0) {
        g_frame_idx[b * KF] = last;
        out[FIDX_OFF + b * KF] = (float)last;
        out[FMASK_OFF + b * T + last] = 1.0f;
    }

    float n[4], md[4];
#pragma unroll
    for (int r = 0; r < 4; r++) {
        int i = lane + 32 * r;
        n[r] = s_GF[i * 128 + i];
        md[r] = __int_as_float(0x7f800000);
    }
    for (int step = 1; step < KF; step++) {
        float nl = s_GF[last * 128 + last];
        float bv = -3e38f; int bi = 0x7fffffff;
#pragma unroll
        for (int r = 0; r < 4; r++) {
            int i = lane + 32 * r;
            float d = n[r] + nl - 2.f * s_GF[last * 128 + i];
            md[r] = fminf(md[r], d);
            if (i == last) md[r] = -1.f;
            if (md[r] > bv) { bv = md[r]; bi = i; }
        }
        last = argmax_redux(bv, bi);
        if (lane == 0) {
            g_frame_idx[b * KF + step] = last;
            out[FIDX_OFF + b * KF + step] = (float)last;
            out[FMASK_OFF + b * T + last] = 1.0f;
        }
    }
}

// ================= K5: split to bf16 hi/lo (float4 in, uint2 out) + zero tmask ====
__global__ void split_kernel(const float* __restrict__ x, float* __restrict__ out) {
    int f = blockIdx.x, row = blockIdx.y;
    int tid = threadIdx.x;
    if (tid < 8) out[TMASK_OFF + (blockIdx.x * 196 + blockIdx.y) * 8 + tid] = 0.f;

    int b = f >> 4, fidx = g_frame_idx[f];
    const float4* src = (const float4*)(x + (size_t)(b * T + fidx) * NTOK * D)
                      + row * 192;
    float4 v = src[tid];
    __nv_bfloat16 h0 = __float2bfloat16(v.x);
    __nv_bfloat16 h1 = __float2bfloat16(v.y);
    __nv_bfloat16 h2 = __float2bfloat16(v.z);
    __nv_bfloat16 h3 = __float2bfloat16(v.w);
    __nv_bfloat16 l0 = __float2bfloat16(v.x - __bfloat162float(h0));
    __nv_bfloat16 l1 = __float2bfloat16(v.y - __bfloat162float(h1));
    __nv_bfloat16 l2 = __float2bfloat16(v.z - __bfloat162float(h2));
    __nv_bfloat16 l3 = __float2bfloat16(v.w - __bfloat162float(h3));
    uint2 hv, lv;
    hv.x = ((uint32_t)__bfloat16_as_ushort(h1) << 16) | __bfloat16_as_ushort(h0);
    hv.y = ((uint32_t)__bfloat16_as_ushort(h3) << 16) | __bfloat16_as_ushort(h2);
    lv.x = ((uint32_t)__bfloat16_as_ushort(l1) << 16) | __bfloat16_as_ushort(l0);
    lv.y = ((uint32_t)__bfloat16_as_ushort(l3) << 16) | __bfloat16_as_ushort(l2);
    ((uint2*)(g_xhi + (size_t)f * PROWS * D))[row * 192 + tid] = hv;
    ((uint2*)(g_xlo + (size_t)f * PROWS * D))[row * 192 + tid] = lv;
}

// ================= K6: token Gram, 2-stage cp.async, 2x2 warp tiling, occ 5 ====
#define GDYN (2 * 4 * 4096)

__global__ __launch_bounds__(128, 5) void gram_hmma_kernel() {
    extern __shared__ __nv_bfloat16 sB[];
    uint32_t sb = smem_u32(sB);
    int tid = threadIdx.x;
    int w = tid >> 5, lane = tid & 31;
    int wm = w & 1, wn = w >> 1;
    int2 tI = c_tiles[blockIdx.x];
    int mi = tI.x, nj = tI.y;
    int f = blockIdx.y;

    const __nv_bfloat16* pAhi = g_xhi + (size_t)f * PROWS * D + (size_t)mi * 64 * D;
    const __nv_bfloat16* pAlo = g_xlo + (size_t)f * PROWS * D + (size_t)mi * 64 * D;
    const __nv_bfloat16* pBhi = g_xhi + (size_t)f * PROWS * D + (size_t)nj * 64 * D;
    const __nv_bfloat16* pBlo = g_xlo + (size_t)f * PROWS * D + (size_t)nj * 64 * D;

    int rbase = tid >> 2, chl = tid & 3;

    float acc[32];   // [au(2)][bj(4)][4]
#pragma unroll
    for (int i = 0; i < 32; i++) acc[i] = 0.f;

    auto issue = [&](int c, int stage) {
        int k0 = c * 32;
#pragma unroll
        for (int i = 0; i < 8; i++) {
            const int t = i >> 1;
            int row = (i & 1) * 32 + rbase;
            const __nv_bfloat16* src =
                (t == 0 ? pAhi : t == 1 ? pAlo : t == 2 ? pBhi : pBlo)
                + (size_t)row * D + k0 + chl * 8;
            uint32_t dst = sb + ((stage * 4 + t) << 12) + row * 64
                         + ((chl ^ ((row >> 1) & 3)) << 4);
            cp16(dst, src);
        }
        asm volatile("cp.async.commit_group;" ::: "memory");
    };

    issue(0, 0);

    int lrow = lane & 15, lhalf = lane >> 4;
    for (int c = 0; c < 24; c++) {
        int buf = c & 1;
        if (c + 1 < 24) {
            issue(c + 1, buf ^ 1);
            asm volatile("cp.async.wait_group 1;" ::: "memory");
        } else {
            asm volatile("cp.async.wait_group 0;" ::: "memory");
        }
        __syncthreads();

        uint32_t tAhi = sb + ((buf * 4 + 0) << 12);
        uint32_t tAlo = sb + ((buf * 4 + 1) << 12);
        uint32_t tBhi = sb + ((buf * 4 + 2) << 12);
        uint32_t tBlo = sb + ((buf * 4 + 3) << 12);
#pragma unroll
        for (int kh = 0; kh < 2; kh++) {
            int ch = kh * 2 + lhalf;
            int ar0 = wm * 32 + lrow, ar1 = ar0 + 16;
            int br0 = wn * 32 + lrow, br1 = br0 + 16;
            uint32_t ah0[4], ah1[4], al0[4], al1[4];
            uint32_t bh0[4], bh1[4], bl0[4], bl1[4];
            uint32_t ao0 = ar0 * 64 + ((ch ^ ((ar0 >> 1) & 3)) << 4);
            uint32_t ao1 = ar1 * 64 + ((ch ^ ((ar1 >> 1) & 3)) << 4);
            uint32_t bo0 = br0 * 64 + ((ch ^ ((br0 >> 1) & 3)) << 4);
            uint32_t bo1 = br1 * 64 + ((ch ^ ((br1 >> 1) & 3)) << 4);
            ldsm4(ah0, tAhi + ao0);
            ldsm4(ah1, tAhi + ao1);
            ldsm4(al0, tAlo + ao0);
            ldsm4(al1, tAlo + ao1);
            ldsm4(bh0, tBhi + bo0);
            ldsm4(bh1, tBhi + bo1);
            ldsm4(bl0, tBlo + bo0);
            ldsm4(bl1, tBlo + bo1);
#pragma unroll
            for (int au = 0; au < 2; au++) {
                const uint32_t* Ah = au ? ah1 : ah0;
                const uint32_t* Al = au ? al1 : al0;
                float* d = acc + au * 16;
                mma16816(d + 0,  Ah, bh0[0], bh0[2]);
                mma16816(d + 4,  Ah, bh0[1], bh0[3]);
                mma16816(d + 8,  Ah, bh1[0], bh1[2]);
                mma16816(d + 12, Ah, bh1[1], bh1[3]);
                mma16816(d + 0,  Ah, bl0[0], bl0[2]);
                mma16816(d + 4,  Ah, bl0[1], bl0[3]);
                mma16816(d + 8,  Ah, bl1[0], bl1[2]);
                mma16816(d + 12, Ah, bl1[1], bl1[3]);
                mma16816(d + 0,  Al, bh0[0], bh0[2]);
                mma16816(d + 4,  Al, bh0[1], bh0[3]);
                mma16816(d + 8,  Al, bh1[0], bh1[2]);
                mma16816(d + 12, Al, bh1[1], bh1[3]);
            }
        }
        __syncthreads();
    }

    // epilogue: direct write; mirror for nj>mi
    int gid = lane >> 2, tig = lane & 3;
    float* G = g_G + (size_t)f * NTOK * NTOK;
    bool mir = (nj > mi);
#pragma unroll
    for (int au = 0; au < 2; au++) {
        int gi0 = mi * 64 + wm * 32 + au * 16 + gid;
        int gi1 = gi0 + 8;
#pragma unroll
        for (int j = 0; j < 4; j++) {
            int gj = nj * 64 + wn * 32 + j * 8 + 2 * tig;
            if (gj < NTOK) {
                const float* a = acc + au * 16 + j * 4;
                float c0 = a[0], c1 = a[1], c2 = a[2], c3 = a[3];
                if (gi0 < NTOK) *(float2*)&G[(size_t)gi0 * NTOK + gj] = make_float2(c0, c1);
                if (gi1 < NTOK) *(float2*)&G[(size_t)gi1 * NTOK + gj] = make_float2(c2, c3);
                if (mir) {
                    if (gi0 < NTOK) {
                        G[(size_t)gj * NTOK + gi0] = c0;
                        G[(size_t)(gj + 1) * NTOK + gi0] = c1;
                    }
                    if (gi1 < NTOK) {
                        G[(size_t)gj * NTOK + gi1] = c2;
                        G[(size_t)(gj + 1) * NTOK + gi1] = c3;
                    }
                }
            }
        }
    }
}

// ================= K7: token FPS (per selected frame) =================
#define GPAD 200
__global__ void token_fps_kernel(float* __restrict__ out) {
    extern __shared__ float Gs[];            // NTOK*GPAD floats
    __shared__ float s_rs[NTOK];

    int f = blockIdx.x, tid = threadIdx.x;   // 224 threads
    const float4* Gp4 = (const float4*)(g_G + (size_t)f * NTOK * NTOK);
    for (int i = tid; i < NTOK * 49; i += 224) {
        int row = i / 49;
        int c4 = i - row * 49;
        *(float4*)&Gs[row * GPAD + (c4 << 2)] = Gp4[i];
    }
    __syncthreads();
    if (tid < NTOK) {
        float r0 = 0.f, r1 = 0.f, r2 = 0.f, r3 = 0.f;
#pragma unroll 4
        for (int j = 0; j < 196; j += 4) {
            r0 += Gs[j * GPAD + tid];
            r1 += Gs[(j + 1) * GPAD + tid];
            r2 += Gs[(j + 2) * GPAD + tid];
            r3 += Gs[(j + 3) * GPAD + tid];
        }
        s_rs[tid] = (r0 + r1) + (r2 + r3);
    }
    __syncthreads();
    if (tid >= 32) return;
    int lane = tid;
    int fidx = g_frame_idx[f];
    int bb = f >> 4;
    size_t tmask_base = TMASK_OFF + ((size_t)(bb * T + fidx)) * NTOK;

    float n[7], md[7];
    float bv = -3e38f; int bi = 0x7fffffff;
#pragma unroll
    for (int q = 0; q < 7; q++) {
        int i = lane + 32 * q;
        bool val = i < NTOK;
        n[q]  = val ? Gs[i * GPAD + i] : 0.f;
        md[q] = val ? __int_as_float(0x7f800000) : -3e38f;
        float v = val ? (n[q] - s_rs[i] * (2.0f / 196.0f)) : -3e38f;
        if (v > bv) { bv = v; bi = i; }
    }
    int last = argmax_redux(bv, bi);
    if (lane == 0) {
        g_token_idx[f * KT] = last;
        out[TIDX_OFF + f * KT] = (float)last;
        out[tmask_base + last] = 1.0f;
    }

    for (int s = 1; s < KT; s++) {
        float nl = Gs[last * GPAD + last];
        bv = -3e38f; bi = 0x7fffffff;
#pragma unroll
        for (int q = 0; q < 7; q++) {
            int i = lane + 32 * q;
            bool val = i < NTOK;
            float g = val ? Gs[last * GPAD + i] : 0.f;
            float d = n[q] + nl - 2.f * g;
            md[q] = fminf(md[q], d);
            if (i == last) md[q] = -1.f;
            float mv = val ? md[q] : -3e38f;
            if (mv > bv) { bv = mv; bi = i; }
        }
        last = argmax_redux(bv, bi);
        if (lane == 0) {
            g_token_idx[f * KT + s] = last;
            out[TIDX_OFF + f * KT + s] = (float)last;
            out[tmask_base + last] = 1.0f;
        }
    }
}

// ================= K8: gather z =================
__global__ void gather_kernel(const float* __restrict__ x, float* __restrict__ out) {
    int row = blockIdx.x;
    int bk = row / KT;
    int t2 = row - bk * KT;
    int b = bk >> 4;
    int fidx = g_frame_idx[bk];
    int tok = g_token_idx[bk * KT + t2];
    const float4* src = (const float4*)(x + (((size_t)(b * T + fidx)) * NTOK + tok) * D);
    float4* dst = (float4*)(out + (size_t)row * D);
    dst[threadIdx.x] = src[threadIdx.x];
}

extern "C" void kernel_launch(void* const* d_in, const int* in_sizes, int n_in,
                              void* d_out, int out_size) {
    const float* x    = (const float*)d_in[0];
    const float* mask = (const float*)d_in[1];
    float* out = (float*)d_out;

    frp_partial_kernel<<<dim3(B * T, 2), 192>>>(x, mask, out);   // 1
    gf_partial_kernel<<<dim3(24, B), 256>>>();                   // 2
    gf_reduce_kernel<<<64, 256>>>();                             // 3

    cudaFuncSetAttribute(novelty_fps_kernel,
                         cudaFuncAttributeMaxDynamicSharedMemorySize, 128 * 128 * 4);
    novelty_fps_kernel<<<B, 256, 128 * 128 * 4>>>(out);          // 4 (ncu slot)

    split_kernel<<<dim3(NF, 196), 192>>>(x, out);                // 5

    cudaFuncSetAttribute(gram_hmma_kernel,
                         cudaFuncAttributeMaxDynamicSharedMemorySize, GDYN);
    gram_hmma_kernel<<<dim3(10, NF), 128, GDYN>>>();             // 6

    size_t dyn = (size_t)NTOK * GPAD * sizeof(float);            // 156,800 B
    cudaFuncSetAttribute(token_fps_kernel,
                         cudaFuncAttributeMaxDynamicSharedMemorySize, (int)dyn);
    token_fps_kernel<<<NF, 224, dyn>>>(out);                     // 7

    gather_kernel<<<B * KF * KT, 192>>>(x, out);                 // 8
}